// round 3
// baseline (speedup 1.0000x reference)
#include <cuda_runtime.h>
#include <math.h>

#define NOISE_SCALE 0.1f
#define NOISE_RATIO 0.3f
#define ADAPTIVE_FACTOR 1.0f
#define MAX_NOISE 1.0f

#define B_ROWS 4096
#define D_COLS 4096
#define C_CLASSES 1000
#define C4 (C_CLASSES / 4)   // 250 float4 per model_output row

__device__ float g_scales[B_ROWS];

// ---------------------------------------------------------------------------
// Kernel 1: warp-per-row softmax confidence.
// Each lane loads up to 8 float4 (8*32=256 >= 250), keeps them in registers,
// does shuffle-max then shuffle-sum of __expf. No shared memory, no bar.sync.
// 8 warps per 256-thread block -> 512 blocks.
// ---------------------------------------------------------------------------
__global__ __launch_bounds__(256) void conf_kernel(const float4* __restrict__ mo4) {
    const int lane = threadIdx.x & 31;
    const int row = blockIdx.x * 8 + (threadIdx.x >> 5);
    const float4* p = mo4 + (long long)row * C4;

    // load slice: indices lane + 32*k, k in [0,8)
    float4 v[8];
    #pragma unroll
    for (int k = 0; k < 8; k++) {
        const int i = lane + 32 * k;
        if (i < C4) v[k] = p[i];
        else        v[k] = make_float4(-INFINITY, -INFINITY, -INFINITY, -INFINITY);
    }

    // max
    float m = -INFINITY;
    #pragma unroll
    for (int k = 0; k < 8; k++)
        m = fmaxf(m, fmaxf(fmaxf(v[k].x, v[k].y), fmaxf(v[k].z, v[k].w)));
    #pragma unroll
    for (int off = 16; off >= 1; off >>= 1)
        m = fmaxf(m, __shfl_xor_sync(0xffffffffu, m, off));

    // sum exp (registers; -INF lanes contribute exp(-inf)=0)
    float s = 0.0f;
    #pragma unroll
    for (int k = 0; k < 8; k++) {
        s += __expf(v[k].x - m) + __expf(v[k].y - m)
           + __expf(v[k].z - m) + __expf(v[k].w - m);
    }
    #pragma unroll
    for (int off = 16; off >= 1; off >>= 1)
        s += __shfl_xor_sync(0xffffffffu, s, off);

    if (lane == 0) {
        float conf = 1.0f / s;
        g_scales[row] = fminf(NOISE_SCALE * (1.0f + ADAPTIVE_FACTOR * conf), MAX_NOISE);
    }
}

// ---------------------------------------------------------------------------
// Kernel 2: elementwise noise add (R1 version: measured 82.8% DRAM).
// ---------------------------------------------------------------------------
__global__ __launch_bounds__(256) void noise_kernel(const float4* __restrict__ x,
                                                    const float4* __restrict__ ru,
                                                    const float4* __restrict__ ns,
                                                    float4* __restrict__ out,
                                                    int n4) {
    int i = blockIdx.x * blockDim.x + threadIdx.x;
    if (i >= n4) return;
    const float s = g_scales[i >> 10];  // D_COLS/4 = 1024 float4 per row
    float4 xv = x[i];
    float4 rv = ru[i];
    float4 nv = ns[i];
    float4 o;
    o.x = xv.x + (rv.x < NOISE_RATIO ? nv.x * s : 0.0f);
    o.y = xv.y + (rv.y < NOISE_RATIO ? nv.y * s : 0.0f);
    o.z = xv.z + (rv.z < NOISE_RATIO ? nv.z * s : 0.0f);
    o.w = xv.w + (rv.w < NOISE_RATIO ? nv.w * s : 0.0f);
    out[i] = o;
}

extern "C" void kernel_launch(void* const* d_in, const int* in_sizes, int n_in,
                              void* d_out, int out_size) {
    const float* x  = (const float*)d_in[0];
    const float* mo = (const float*)d_in[1];
    const float* ru = (const float*)d_in[2];
    const float* ns = (const float*)d_in[3];
    float* out = (float*)d_out;

    conf_kernel<<<B_ROWS / 8, 256>>>((const float4*)mo);

    const int n4 = (B_ROWS * D_COLS) / 4;  // 4,194,304
    noise_kernel<<<(n4 + 255) / 256, 256>>>((const float4*)x, (const float4*)ru,
                                            (const float4*)ns, (float4*)out, n4);
}

// round 4
// speedup vs baseline: 1.2076x; 1.2076x over previous
#include <cuda_runtime.h>
#include <math.h>

#define NOISE_SCALE 0.1f
#define NOISE_RATIO 0.3f
#define ADAPTIVE_FACTOR 1.0f
#define MAX_NOISE 1.0f

#define B_ROWS 4096
#define D_COLS 4096
#define C_CLASSES 1000
#define C4 (C_CLASSES / 4)   // 250 float4 per model_output row
#define D4 (D_COLS / 4)      // 1024 float4 per data row
#define NCHUNK (D4 / 256)    // 4 chunks of 256 float4 per row

// One block per row. Prefetch ALL elementwise loads into registers, then do
// the softmax-confidence reduction (overlapping its latency with the loads),
// then apply scale + store.
__global__ __launch_bounds__(256) void fused_kernel(const float4* __restrict__ x,
                                                    const float4* __restrict__ mo4,
                                                    const float4* __restrict__ ru,
                                                    const float4* __restrict__ ns,
                                                    float4* __restrict__ out) {
    const int row = blockIdx.x;
    const int tid = threadIdx.x;
    const int lane = tid & 31;
    const int warp = tid >> 5;

    __shared__ float sred[8];
    __shared__ float s_scale;

    // ---- 1) logits slice first (reduction depends only on this) ----
    float4 v;
    const bool have = (tid < C4);
    if (have) v = mo4[(long long)row * C4 + tid];
    else      v = make_float4(-INFINITY, -INFINITY, -INFINITY, -INFINITY);

    // ---- 2) prefetch all elementwise chunks (12 LDG.128 in flight) ----
    const long long base = (long long)row * D4;
    float4 xv[NCHUNK], rv[NCHUNK], nv[NCHUNK];
    #pragma unroll
    for (int j = 0; j < NCHUNK; j++) {
        const long long i = base + tid + j * 256;
        xv[j] = __ldcs(&x[i]);
        rv[j] = __ldcs(&ru[i]);
        nv[j] = __ldcs(&ns[i]);
    }

    // ---- 3) row max (waits only on v) ----
    float m = fmaxf(fmaxf(v.x, v.y), fmaxf(v.z, v.w));
    #pragma unroll
    for (int off = 16; off >= 1; off >>= 1)
        m = fmaxf(m, __shfl_xor_sync(0xffffffffu, m, off));
    if (lane == 0) sred[warp] = m;
    __syncthreads();
    if (warp == 0) {
        float mm = sred[lane & 7];
        #pragma unroll
        for (int off = 4; off >= 1; off >>= 1)
            mm = fmaxf(mm, __shfl_xor_sync(0xffffffffu, mm, off));
        if (lane == 0) sred[0] = mm;
    }
    __syncthreads();
    m = sred[0];

    // ---- 4) sum exp(l - m) ----
    float s = 0.0f;
    if (have)
        s = __expf(v.x - m) + __expf(v.y - m) + __expf(v.z - m) + __expf(v.w - m);
    #pragma unroll
    for (int off = 16; off >= 1; off >>= 1)
        s += __shfl_xor_sync(0xffffffffu, s, off);
    __syncthreads();
    if (lane == 0) sred[warp] = s;
    __syncthreads();
    if (warp == 0) {
        float ss = sred[lane & 7];
        #pragma unroll
        for (int off = 4; off >= 1; off >>= 1)
            ss += __shfl_xor_sync(0xffffffffu, ss, off);
        if (lane == 0) {
            float conf = 1.0f / ss;
            s_scale = fminf(NOISE_SCALE * (1.0f + ADAPTIVE_FACTOR * conf), MAX_NOISE);
        }
    }
    __syncthreads();
    const float scale = s_scale;

    // ---- 5) apply + store (data already resident in registers) ----
    #pragma unroll
    for (int j = 0; j < NCHUNK; j++) {
        const long long i = base + tid + j * 256;
        float4 o;
        o.x = xv[j].x + (rv[j].x < NOISE_RATIO ? nv[j].x * scale : 0.0f);
        o.y = xv[j].y + (rv[j].y < NOISE_RATIO ? nv[j].y * scale : 0.0f);
        o.z = xv[j].z + (rv[j].z < NOISE_RATIO ? nv[j].z * scale : 0.0f);
        o.w = xv[j].w + (rv[j].w < NOISE_RATIO ? nv[j].w * scale : 0.0f);
        __stcs(&out[i], o);
    }
}

extern "C" void kernel_launch(void* const* d_in, const int* in_sizes, int n_in,
                              void* d_out, int out_size) {
    const float* x  = (const float*)d_in[0];
    const float* mo = (const float*)d_in[1];
    const float* ru = (const float*)d_in[2];
    const float* ns = (const float*)d_in[3];
    float* out = (float*)d_out;

    fused_kernel<<<B_ROWS, 256>>>((const float4*)x, (const float4*)mo,
                                  (const float4*)ru, (const float4*)ns,
                                  (float4*)out);
}